// round 1
// baseline (speedup 1.0000x reference)
#include <cuda_runtime.h>
#include <math.h>

#define BB 2
#define SS 2048
#define HIDN 1280
#define NH 20
#define HD 64

// Scratch (alloc-free rule: __device__ globals)
__device__ float g_Q[BB*NH*SS*HD];
__device__ float g_K[BB*NH*SS*HD];
__device__ float g_V[BB*NH*SS*HD];
__device__ float g_cos[SS*32];
__device__ float g_sin[SS*32];

// ---------------------------------------------------------------------------
// RoPE cos/sin table (double precision; matches fp32 reference to ~1e-4)
// ---------------------------------------------------------------------------
__global__ void sincos_kernel() {
    int idx = blockIdx.x * blockDim.x + threadIdx.x;
    if (idx >= SS * 32) return;
    int j = idx & 31;
    int s = idx >> 5;
    double invf = exp(-((double)j / 32.0) * log(10000.0));
    double a = (double)s * invf;
    g_cos[idx] = (float)cos(a);
    g_sin[idx] = (float)sin(a);
}

// ---------------------------------------------------------------------------
// Fused QKV projection GEMM.
// X: [M=4096, K=1280] row-major. W*: [1280, 1280] row-major (k,n).
// Logical N = 3840; blockIdx.x tile selects which weight (1280/128 = 10 tiles each).
// Output written in [B, H, S, D] layout into g_Q/g_K/g_V.
// ---------------------------------------------------------------------------
__global__ __launch_bounds__(256) void qkv_gemm(
    const float* __restrict__ X,
    const float* __restrict__ Wq, const float* __restrict__ bq,
    const float* __restrict__ Wk, const float* __restrict__ bk,
    const float* __restrict__ Wv, const float* __restrict__ bv)
{
    __shared__ float As[16][132];
    __shared__ float Bs[16][132];

    const int n0g   = blockIdx.x * 128;       // 0..3712
    const int m0    = blockIdx.y * 128;       // 0..3968
    const int which = n0g / HIDN;             // 0=Q, 1=K, 2=V
    const int ncol0 = n0g % HIDN;

    const float* W    = (which == 0) ? Wq : (which == 1 ? Wk : Wv);
    const float* bias = (which == 0) ? bq : (which == 1 ? bk : bv);
    float*       Out  = (which == 0) ? g_Q : (which == 1 ? g_K : g_V);

    const int tid = threadIdx.x;
    const int tx  = tid & 15;
    const int ty  = tid >> 4;

    float acc[8][8];
    #pragma unroll
    for (int i = 0; i < 8; i++)
        #pragma unroll
        for (int j = 0; j < 8; j++) acc[i][j] = 0.0f;

    const int a_row = tid >> 2;          // 0..63
    const int a_col = (tid & 3) << 2;    // 0,4,8,12
    const int b_row = tid >> 5;          // 0..7
    const int b_col = (tid & 31) << 2;   // 0..124

    for (int k0 = 0; k0 < HIDN; k0 += 16) {
        #pragma unroll
        for (int r = 0; r < 2; r++) {
            int m = a_row + r * 64;
            float4 v = *(const float4*)&X[(m0 + m) * HIDN + k0 + a_col];
            As[a_col + 0][m] = v.x;
            As[a_col + 1][m] = v.y;
            As[a_col + 2][m] = v.z;
            As[a_col + 3][m] = v.w;
        }
        #pragma unroll
        for (int r = 0; r < 2; r++) {
            int kk = b_row + r * 8;
            *(float4*)&Bs[kk][b_col] =
                *(const float4*)&W[(k0 + kk) * HIDN + ncol0 + b_col];
        }
        __syncthreads();

        #pragma unroll
        for (int kk = 0; kk < 16; kk++) {
            float ra[8], rb[8];
            *(float4*)&ra[0] = *(float4*)&As[kk][ty * 4];
            *(float4*)&ra[4] = *(float4*)&As[kk][64 + ty * 4];
            *(float4*)&rb[0] = *(float4*)&Bs[kk][tx * 4];
            *(float4*)&rb[4] = *(float4*)&Bs[kk][64 + tx * 4];
            #pragma unroll
            for (int i = 0; i < 8; i++)
                #pragma unroll
                for (int j = 0; j < 8; j++)
                    acc[i][j] += ra[i] * rb[j];
        }
        __syncthreads();
    }

    // Epilogue: add bias, scatter into [B, H, S, D]
    #pragma unroll
    for (int i = 0; i < 8; i++) {
        int m = m0 + ((i < 4) ? (ty * 4 + i) : (64 + ty * 4 + (i - 4)));
        int b = m >> 11;       // m / 2048
        int s = m & 2047;
        #pragma unroll
        for (int j = 0; j < 8; j++) {
            int col = ncol0 + ((j < 4) ? (tx * 4 + j) : (64 + tx * 4 + (j - 4)));
            int h = col >> 6;
            int d = col & 63;
            Out[(((b * NH + h) * SS) + s) * HD + d] = acc[i][j] + bias[col];
        }
    }
}

// ---------------------------------------------------------------------------
// RoPE (and query scaling by D^-0.5; scaling commutes with the rotation).
// One thread per (b,h,s,j<32) pair, rotating both Q and K.
// ---------------------------------------------------------------------------
__global__ __launch_bounds__(256) void rope_kernel() {
    int idx = blockIdx.x * blockDim.x + threadIdx.x;   // < BB*NH*SS*32
    int j  = idx & 31;
    int s  = (idx >> 5) & (SS - 1);
    int bh = idx >> 16;
    float c  = g_cos[(s << 5) + j];
    float sn = g_sin[(s << 5) + j];
    int base = (bh * SS + s) * HD;
    const float scale = 0.125f;   // 64^-0.5

    float q1 = g_Q[base + j], q2 = g_Q[base + j + 32];
    g_Q[base + j]      = (q1 * c - q2 * sn) * scale;
    g_Q[base + j + 32] = (q2 * c + q1 * sn) * scale;

    float k1 = g_K[base + j], k2 = g_K[base + j + 32];
    g_K[base + j]      = k1 * c - k2 * sn;
    g_K[base + j + 32] = k2 * c + k1 * sn;
}

// ---------------------------------------------------------------------------
// Flash-attention style fp32 attention.
// Block: 256 threads (16x16), BQ=64 query rows, BKV=32 key columns / iter.
// Thread (ty,tx): 4 q-rows (ty*4..), 2 score cols (tx*2..), 4 d-cols (tx*4..).
// ---------------------------------------------------------------------------
__global__ __launch_bounds__(256) void attn_kernel(
    const float* __restrict__ mask, float* __restrict__ out)
{
    __shared__ float Qs[64][68];
    __shared__ float Ks[32][68];
    __shared__ float Vs[32][64];
    __shared__ float Ps[64][36];

    const int bh = blockIdx.y;
    const int b  = bh / NH;
    const int h  = bh % NH;
    const int q0 = blockIdx.x * 64;

    const float* Qb = g_Q + (size_t)bh * SS * HD;
    const float* Kb = g_K + (size_t)bh * SS * HD;
    const float* Vb = g_V + (size_t)bh * SS * HD;
    const float* mk = mask + b * SS;

    const int tid = threadIdx.x;
    const int tx  = tid & 15;
    const int ty  = tid >> 4;

    // Load Q tile (64 x 64)
    for (int i = tid; i < 1024; i += 256) {
        int r = i >> 4, c = (i & 15) << 2;
        *(float4*)&Qs[r][c] = *(const float4*)&Qb[(q0 + r) * HD + c];
    }

    float o[4][4];
    #pragma unroll
    for (int i = 0; i < 4; i++)
        #pragma unroll
        for (int j = 0; j < 4; j++) o[i][j] = 0.0f;
    float mrow[4] = {-1e30f, -1e30f, -1e30f, -1e30f};
    float lrow[4] = {0.0f, 0.0f, 0.0f, 0.0f};

    for (int k0 = 0; k0 < SS; k0 += 32) {
        __syncthreads();   // protect Ks/Vs (prev PV) and Ps (prev reads)
        // Load K, V tiles (32 x 64 each) — 512 float4 each, 2 per thread
        for (int i = tid; i < 512; i += 256) {
            int r = i >> 4, c = (i & 15) << 2;
            *(float4*)&Ks[r][c] = *(const float4*)&Kb[(k0 + r) * HD + c];
            *(float4*)&Vs[r][c] = *(const float4*)&Vb[(k0 + r) * HD + c];
        }
        __syncthreads();

        // Scores: 4 rows x 2 cols per thread, init with attention mask
        float sc[4][2];
        {
            float mv0 = mk[k0 + tx * 2 + 0];
            float mv1 = mk[k0 + tx * 2 + 1];
            #pragma unroll
            for (int i = 0; i < 4; i++) { sc[i][0] = mv0; sc[i][1] = mv1; }
        }
        #pragma unroll
        for (int dd = 0; dd < 64; dd += 4) {
            float4 qv[4], kv[2];
            #pragma unroll
            for (int i = 0; i < 4; i++) qv[i] = *(const float4*)&Qs[ty * 4 + i][dd];
            #pragma unroll
            for (int j = 0; j < 2; j++) kv[j] = *(const float4*)&Ks[tx * 2 + j][dd];
            #pragma unroll
            for (int i = 0; i < 4; i++)
                #pragma unroll
                for (int j = 0; j < 2; j++)
                    sc[i][j] += qv[i].x * kv[j].x + qv[i].y * kv[j].y
                              + qv[i].z * kv[j].z + qv[i].w * kv[j].w;
        }

        // Online softmax (row groups = 16 tx lanes)
        #pragma unroll
        for (int i = 0; i < 4; i++) {
            float mx = fmaxf(sc[i][0], sc[i][1]);
            #pragma unroll
            for (int off = 8; off >= 1; off >>= 1)
                mx = fmaxf(mx, __shfl_xor_sync(0xffffffffu, mx, off, 16));
            float mnew = fmaxf(mrow[i], mx);
            float corr = __expf(mrow[i] - mnew);
            mrow[i] = mnew;
            float p0 = __expf(sc[i][0] - mnew);
            float p1 = __expf(sc[i][1] - mnew);
            float rs = p0 + p1;
            #pragma unroll
            for (int off = 8; off >= 1; off >>= 1)
                rs += __shfl_xor_sync(0xffffffffu, rs, off, 16);
            lrow[i] = lrow[i] * corr + rs;
            #pragma unroll
            for (int j = 0; j < 4; j++) o[i][j] *= corr;
            Ps[ty * 4 + i][tx * 2 + 0] = p0;
            Ps[ty * 4 + i][tx * 2 + 1] = p1;
        }
        __syncthreads();

        // O += P @ V  (thread: 4 rows x 4 d-cols)
        #pragma unroll
        for (int kc = 0; kc < 32; kc += 4) {
            float4 vv[4];
            #pragma unroll
            for (int u = 0; u < 4; u++) vv[u] = *(const float4*)&Vs[kc + u][tx * 4];
            #pragma unroll
            for (int i = 0; i < 4; i++) {
                float4 pv = *(const float4*)&Ps[ty * 4 + i][kc];
                o[i][0] += pv.x * vv[0].x + pv.y * vv[1].x + pv.z * vv[2].x + pv.w * vv[3].x;
                o[i][1] += pv.x * vv[0].y + pv.y * vv[1].y + pv.z * vv[2].y + pv.w * vv[3].y;
                o[i][2] += pv.x * vv[0].z + pv.y * vv[1].z + pv.z * vv[2].z + pv.w * vv[3].z;
                o[i][3] += pv.x * vv[0].w + pv.y * vv[1].w + pv.z * vv[2].w + pv.w * vv[3].w;
            }
        }
    }

    // Normalize, write out in [B, S, H*D]
    #pragma unroll
    for (int i = 0; i < 4; i++) {
        float inv = 1.0f / lrow[i];
        int srow = q0 + ty * 4 + i;
        int obase = (b * SS + srow) * HIDN + h * HD + tx * 4;
        float4 v;
        v.x = o[i][0] * inv;
        v.y = o[i][1] * inv;
        v.z = o[i][2] * inv;
        v.w = o[i][3] * inv;
        *(float4*)&out[obase] = v;
    }
}

// ---------------------------------------------------------------------------
extern "C" void kernel_launch(void* const* d_in, const int* in_sizes, int n_in,
                              void* d_out, int out_size) {
    const float* hs   = (const float*)d_in[0];
    const float* mask = (const float*)d_in[1];
    const float* Wq   = (const float*)d_in[2];
    const float* bq   = (const float*)d_in[3];
    const float* Wk   = (const float*)d_in[4];
    const float* bk   = (const float*)d_in[5];
    const float* Wv   = (const float*)d_in[6];
    const float* bv   = (const float*)d_in[7];
    float* out = (float*)d_out;

    sincos_kernel<<<(SS * 32 + 255) / 256, 256>>>();
    qkv_gemm<<<dim3(30, 32), 256>>>(hs, Wq, bq, Wk, bk, Wv, bv);
    rope_kernel<<<(BB * NH * SS * 32) / 256, 256>>>();
    attn_kernel<<<dim3(SS / 64, BB * NH), 256>>>(mask, out);
}

// round 2
// speedup vs baseline: 1.2998x; 1.2998x over previous
#include <cuda_runtime.h>
#include <math.h>

#define BB 2
#define SS 2048
#define HIDN 1280
#define NH 20
#define HD 64

// Scratch (alloc-free rule: __device__ globals)
__device__ float g_Q[BB*NH*SS*HD];
__device__ float g_K[BB*NH*SS*HD];
__device__ float g_V[BB*NH*SS*HD];
__device__ float g_cos[SS*32];
__device__ float g_sin[SS*32];

// ---------------------------------------------------------------------------
// RoPE cos/sin table (double precision; matches fp32 reference to ~1e-4)
// ---------------------------------------------------------------------------
__global__ void sincos_kernel() {
    int idx = blockIdx.x * blockDim.x + threadIdx.x;
    if (idx >= SS * 32) return;
    int j = idx & 31;
    int s = idx >> 5;
    double invf = exp(-((double)j / 32.0) * log(10000.0));
    double a = (double)s * invf;
    g_cos[idx] = (float)cos(a);
    g_sin[idx] = (float)sin(a);
}

// ---------------------------------------------------------------------------
// tf32 helpers
// ---------------------------------------------------------------------------
__device__ __forceinline__ float to_tf32(float x) {
    float r;
    asm("cvt.rna.tf32.f32 %0, %1;" : "=f"(r) : "f"(x));
    return r;
}

__device__ __forceinline__ void mma_tf32(float c[4], const float a[4],
                                         float b0, float b1) {
    asm volatile(
        "mma.sync.aligned.m16n8k8.row.col.f32.tf32.tf32.f32 "
        "{%0,%1,%2,%3}, {%4,%5,%6,%7}, {%8,%9}, {%0,%1,%2,%3};"
        : "+f"(c[0]), "+f"(c[1]), "+f"(c[2]), "+f"(c[3])
        : "r"(__float_as_uint(a[0])), "r"(__float_as_uint(a[1])),
          "r"(__float_as_uint(a[2])), "r"(__float_as_uint(a[3])),
          "r"(__float_as_uint(b0)),  "r"(__float_as_uint(b1)));
}

// ---------------------------------------------------------------------------
// Fused QKV projection GEMM — tf32 tensor cores (mma.sync m16n8k8).
// X: [M=4096, K=1280] row-major. W*: [1280, 1280] row-major (k, n).
// Logical N = 3840; blockIdx.x selects which weight (10 tiles of 128 each).
// Block tile 128x128, 8 warps as 2(m) x 4(n), warp tile 64x32.
// Output scattered into [B, H, S, D] layout in g_Q/g_K/g_V, bias added.
// ---------------------------------------------------------------------------
__global__ __launch_bounds__(256, 2) void qkv_gemm_tf32(
    const float* __restrict__ X,
    const float* __restrict__ Wq, const float* __restrict__ bq,
    const float* __restrict__ Wk, const float* __restrict__ bk,
    const float* __restrict__ Wv, const float* __restrict__ bv)
{
    __shared__ float As[128][36];    // [m][k] pad 36 -> conflict-free frags
    __shared__ float Bs[32][136];    // [k][n] pad 136 -> conflict-free frags

    const int n0g   = blockIdx.x * 128;
    const int m0    = blockIdx.y * 128;
    const int which = n0g / HIDN;             // 0=Q, 1=K, 2=V
    const int ncol0 = n0g % HIDN;

    const float* W    = (which == 0) ? Wq : (which == 1 ? Wk : Wv);
    const float* bias = (which == 0) ? bq : (which == 1 ? bk : bv);
    float*       Out  = (which == 0) ? g_Q : (which == 1 ? g_K : g_V);

    const int tid  = threadIdx.x;
    const int lane = tid & 31;
    const int warp = tid >> 5;
    const int wm   = (warp & 1) * 64;
    const int wn   = (warp >> 1) * 32;
    const int g    = lane >> 2;     // groupID (0..7)
    const int t4   = lane & 3;      // threadID_in_group (0..3)

    float acc[4][4][4];
    #pragma unroll
    for (int mt = 0; mt < 4; mt++)
        #pragma unroll
        for (int nt = 0; nt < 4; nt++)
            #pragma unroll
            for (int i = 0; i < 4; i++) acc[mt][nt][i] = 0.0f;

    const int a_r  = tid >> 3;          // 0..31 (+32*pass)
    const int a_k  = (tid & 7) * 4;     // 0,4,...,28
    const int b_n  = lane * 4;          // 0..124

    for (int k0 = 0; k0 < HIDN; k0 += 32) {
        // Stage A: 128 x 32 (coalesced global, conflict-free STS.128)
        #pragma unroll
        for (int p = 0; p < 4; p++) {
            int r = a_r + p * 32;
            float4 v = *(const float4*)&X[(m0 + r) * HIDN + k0 + a_k];
            v.x = to_tf32(v.x); v.y = to_tf32(v.y);
            v.z = to_tf32(v.z); v.w = to_tf32(v.w);
            *(float4*)&As[r][a_k] = v;
        }
        // Stage B: 32 x 128 (coalesced global, conflict-free STS.128)
        #pragma unroll
        for (int p = 0; p < 4; p++) {
            int kk = warp + p * 8;
            float4 v = *(const float4*)&W[(k0 + kk) * HIDN + ncol0 + b_n];
            v.x = to_tf32(v.x); v.y = to_tf32(v.y);
            v.z = to_tf32(v.z); v.w = to_tf32(v.w);
            *(float4*)&Bs[kk][b_n] = v;
        }
        __syncthreads();

        #pragma unroll
        for (int kc = 0; kc < 4; kc++) {
            const int kr = kc * 8;
            float a[4][4];
            #pragma unroll
            for (int mt = 0; mt < 4; mt++) {
                int mr = wm + mt * 16;
                a[mt][0] = As[mr + g    ][kr + t4    ];
                a[mt][1] = As[mr + g + 8][kr + t4    ];
                a[mt][2] = As[mr + g    ][kr + t4 + 4];
                a[mt][3] = As[mr + g + 8][kr + t4 + 4];
            }
            #pragma unroll
            for (int nt = 0; nt < 4; nt++) {
                float b0 = Bs[kr + t4    ][wn + nt * 8 + g];
                float b1 = Bs[kr + t4 + 4][wn + nt * 8 + g];
                #pragma unroll
                for (int mt = 0; mt < 4; mt++)
                    mma_tf32(acc[mt][nt], a[mt], b0, b1);
            }
        }
        __syncthreads();
    }

    // Epilogue: bias + scatter into [B, H, S, D].
    // c0=(g,2t), c1=(g,2t+1), c2=(g+8,2t), c3=(g+8,2t+1)
    #pragma unroll
    for (int mt = 0; mt < 4; mt++) {
        #pragma unroll
        for (int nt = 0; nt < 4; nt++) {
            int col = ncol0 + wn + nt * 8 + t4 * 2;   // even, pair within head
            int h = col >> 6;
            int d = col & 63;
            float bi0 = bias[col];
            float bi1 = bias[col + 1];
            #pragma unroll
            for (int rh = 0; rh < 2; rh++) {
                int m = m0 + wm + mt * 16 + g + rh * 8;
                int b = m >> 11;
                int s = m & 2047;
                float2 v;
                v.x = acc[mt][nt][rh * 2 + 0] + bi0;
                v.y = acc[mt][nt][rh * 2 + 1] + bi1;
                *(float2*)&Out[(((b * NH + h) * SS) + s) * HD + d] = v;
            }
        }
    }
}

// ---------------------------------------------------------------------------
// RoPE (and query scaling by D^-0.5; scaling commutes with the rotation).
// ---------------------------------------------------------------------------
__global__ __launch_bounds__(256) void rope_kernel() {
    int idx = blockIdx.x * blockDim.x + threadIdx.x;   // < BB*NH*SS*32
    int j  = idx & 31;
    int s  = (idx >> 5) & (SS - 1);
    int bh = idx >> 16;
    float c  = g_cos[(s << 5) + j];
    float sn = g_sin[(s << 5) + j];
    int base = (bh * SS + s) * HD;
    const float scale = 0.125f;   // 64^-0.5

    float q1 = g_Q[base + j], q2 = g_Q[base + j + 32];
    g_Q[base + j]      = (q1 * c - q2 * sn) * scale;
    g_Q[base + j + 32] = (q2 * c + q1 * sn) * scale;

    float k1 = g_K[base + j], k2 = g_K[base + j + 32];
    g_K[base + j]      = k1 * c - k2 * sn;
    g_K[base + j + 32] = k2 * c + k1 * sn;
}

// ---------------------------------------------------------------------------
// Flash-attention style fp32 attention (unchanged this round).
// ---------------------------------------------------------------------------
__global__ __launch_bounds__(256) void attn_kernel(
    const float* __restrict__ mask, float* __restrict__ out)
{
    __shared__ float Qs[64][68];
    __shared__ float Ks[32][68];
    __shared__ float Vs[32][64];
    __shared__ float Ps[64][36];

    const int bh = blockIdx.y;
    const int b  = bh / NH;
    const int h  = bh % NH;
    const int q0 = blockIdx.x * 64;

    const float* Qb = g_Q + (size_t)bh * SS * HD;
    const float* Kb = g_K + (size_t)bh * SS * HD;
    const float* Vb = g_V + (size_t)bh * SS * HD;
    const float* mk = mask + b * SS;

    const int tid = threadIdx.x;
    const int tx  = tid & 15;
    const int ty  = tid >> 4;

    for (int i = tid; i < 1024; i += 256) {
        int r = i >> 4, c = (i & 15) << 2;
        *(float4*)&Qs[r][c] = *(const float4*)&Qb[(q0 + r) * HD + c];
    }

    float o[4][4];
    #pragma unroll
    for (int i = 0; i < 4; i++)
        #pragma unroll
        for (int j = 0; j < 4; j++) o[i][j] = 0.0f;
    float mrow[4] = {-1e30f, -1e30f, -1e30f, -1e30f};
    float lrow[4] = {0.0f, 0.0f, 0.0f, 0.0f};

    for (int k0 = 0; k0 < SS; k0 += 32) {
        __syncthreads();
        for (int i = tid; i < 512; i += 256) {
            int r = i >> 4, c = (i & 15) << 2;
            *(float4*)&Ks[r][c] = *(const float4*)&Kb[(k0 + r) * HD + c];
            *(float4*)&Vs[r][c] = *(const float4*)&Vb[(k0 + r) * HD + c];
        }
        __syncthreads();

        float sc[4][2];
        {
            float mv0 = mk[k0 + tx * 2 + 0];
            float mv1 = mk[k0 + tx * 2 + 1];
            #pragma unroll
            for (int i = 0; i < 4; i++) { sc[i][0] = mv0; sc[i][1] = mv1; }
        }
        #pragma unroll
        for (int dd = 0; dd < 64; dd += 4) {
            float4 qv[4], kv[2];
            #pragma unroll
            for (int i = 0; i < 4; i++) qv[i] = *(const float4*)&Qs[ty * 4 + i][dd];
            #pragma unroll
            for (int j = 0; j < 2; j++) kv[j] = *(const float4*)&Ks[tx * 2 + j][dd];
            #pragma unroll
            for (int i = 0; i < 4; i++)
                #pragma unroll
                for (int j = 0; j < 2; j++)
                    sc[i][j] += qv[i].x * kv[j].x + qv[i].y * kv[j].y
                              + qv[i].z * kv[j].z + qv[i].w * kv[j].w;
        }

        #pragma unroll
        for (int i = 0; i < 4; i++) {
            float mx = fmaxf(sc[i][0], sc[i][1]);
            #pragma unroll
            for (int off = 8; off >= 1; off >>= 1)
                mx = fmaxf(mx, __shfl_xor_sync(0xffffffffu, mx, off, 16));
            float mnew = fmaxf(mrow[i], mx);
            float corr = __expf(mrow[i] - mnew);
            mrow[i] = mnew;
            float p0 = __expf(sc[i][0] - mnew);
            float p1 = __expf(sc[i][1] - mnew);
            float rs = p0 + p1;
            #pragma unroll
            for (int off = 8; off >= 1; off >>= 1)
                rs += __shfl_xor_sync(0xffffffffu, rs, off, 16);
            lrow[i] = lrow[i] * corr + rs;
            #pragma unroll
            for (int j = 0; j < 4; j++) o[i][j] *= corr;
            Ps[ty * 4 + i][tx * 2 + 0] = p0;
            Ps[ty * 4 + i][tx * 2 + 1] = p1;
        }
        __syncthreads();

        #pragma unroll
        for (int kc = 0; kc < 32; kc += 4) {
            float4 vv[4];
            #pragma unroll
            for (int u = 0; u < 4; u++) vv[u] = *(const float4*)&Vs[kc + u][tx * 4];
            #pragma unroll
            for (int i = 0; i < 4; i++) {
                float4 pv = *(const float4*)&Ps[ty * 4 + i][kc];
                o[i][0] += pv.x * vv[0].x + pv.y * vv[1].x + pv.z * vv[2].x + pv.w * vv[3].x;
                o[i][1] += pv.x * vv[0].y + pv.y * vv[1].y + pv.z * vv[2].y + pv.w * vv[3].y;
                o[i][2] += pv.x * vv[0].z + pv.y * vv[1].z + pv.z * vv[2].z + pv.w * vv[3].z;
                o[i][3] += pv.x * vv[0].w + pv.y * vv[1].w + pv.z * vv[2].w + pv.w * vv[3].w;
            }
        }
    }

    #pragma unroll
    for (int i = 0; i < 4; i++) {
        float inv = 1.0f / lrow[i];
        int srow = q0 + ty * 4 + i;
        int obase = (b * SS + srow) * HIDN + h * HD + tx * 4;
        float4 v;
        v.x = o[i][0] * inv;
        v.y = o[i][1] * inv;
        v.z = o[i][2] * inv;
        v.w = o[i][3] * inv;
        *(float4*)&out[obase] = v;
    }
}

// ---------------------------------------------------------------------------
extern "C" void kernel_launch(void* const* d_in, const int* in_sizes, int n_in,
                              void* d_out, int out_size) {
    const float* hs   = (const float*)d_in[0];
    const float* mask = (const float*)d_in[1];
    const float* Wq   = (const float*)d_in[2];
    const float* bq   = (const float*)d_in[3];
    const float* Wk   = (const float*)d_in[4];
    const float* bk   = (const float*)d_in[5];
    const float* Wv   = (const float*)d_in[6];
    const float* bv   = (const float*)d_in[7];
    float* out = (float*)d_out;

    sincos_kernel<<<(SS * 32 + 255) / 256, 256>>>();
    qkv_gemm_tf32<<<dim3(30, 32), 256>>>(hs, Wq, bq, Wk, bk, Wv, bv);
    rope_kernel<<<(BB * NH * SS * 32) / 256, 256>>>();
    attn_kernel<<<dim3(SS / 64, BB * NH), 256>>>(mask, out);
}

// round 3
// speedup vs baseline: 2.7901x; 2.1466x over previous
#include <cuda_runtime.h>
#include <math.h>

#define BB 2
#define SS 2048
#define HIDN 1280
#define NH 20
#define HD 64

// Scratch (alloc-free rule: __device__ globals)
__device__ float g_Q[BB*NH*SS*HD];
__device__ float g_K[BB*NH*SS*HD];
__device__ float g_V[BB*NH*SS*HD];
__device__ float g_cos[SS*32];
__device__ float g_sin[SS*32];

// ---------------------------------------------------------------------------
// RoPE cos/sin table
// ---------------------------------------------------------------------------
__global__ void sincos_kernel() {
    int idx = blockIdx.x * blockDim.x + threadIdx.x;
    if (idx >= SS * 32) return;
    int j = idx & 31;
    int s = idx >> 5;
    double invf = exp(-((double)j / 32.0) * log(10000.0));
    double a = (double)s * invf;
    g_cos[idx] = (float)cos(a);
    g_sin[idx] = (float)sin(a);
}

// ---------------------------------------------------------------------------
// tf32 helpers
// ---------------------------------------------------------------------------
__device__ __forceinline__ float to_tf32(float x) {
    float r;
    asm("cvt.rna.tf32.f32 %0, %1;" : "=f"(r) : "f"(x));
    return r;
}

__device__ __forceinline__ void mma_tf32(float c[4], const float a[4],
                                         float b0, float b1) {
    asm volatile(
        "mma.sync.aligned.m16n8k8.row.col.f32.tf32.tf32.f32 "
        "{%0,%1,%2,%3}, {%4,%5,%6,%7}, {%8,%9}, {%0,%1,%2,%3};"
        : "+f"(c[0]), "+f"(c[1]), "+f"(c[2]), "+f"(c[3])
        : "r"(__float_as_uint(a[0])), "r"(__float_as_uint(a[1])),
          "r"(__float_as_uint(a[2])), "r"(__float_as_uint(a[3])),
          "r"(__float_as_uint(b0)),  "r"(__float_as_uint(b1)));
}

// ---------------------------------------------------------------------------
// Fused QKV projection GEMM — tf32 tensor cores (unchanged from R2).
// ---------------------------------------------------------------------------
__global__ __launch_bounds__(256, 2) void qkv_gemm_tf32(
    const float* __restrict__ X,
    const float* __restrict__ Wq, const float* __restrict__ bq,
    const float* __restrict__ Wk, const float* __restrict__ bk,
    const float* __restrict__ Wv, const float* __restrict__ bv)
{
    __shared__ float As[128][36];
    __shared__ float Bs[32][136];

    const int n0g   = blockIdx.x * 128;
    const int m0    = blockIdx.y * 128;
    const int which = n0g / HIDN;
    const int ncol0 = n0g % HIDN;

    const float* W    = (which == 0) ? Wq : (which == 1 ? Wk : Wv);
    const float* bias = (which == 0) ? bq : (which == 1 ? bk : bv);
    float*       Out  = (which == 0) ? g_Q : (which == 1 ? g_K : g_V);

    const int tid  = threadIdx.x;
    const int lane = tid & 31;
    const int warp = tid >> 5;
    const int wm   = (warp & 1) * 64;
    const int wn   = (warp >> 1) * 32;
    const int g    = lane >> 2;
    const int t4   = lane & 3;

    float acc[4][4][4];
    #pragma unroll
    for (int mt = 0; mt < 4; mt++)
        #pragma unroll
        for (int nt = 0; nt < 4; nt++)
            #pragma unroll
            for (int i = 0; i < 4; i++) acc[mt][nt][i] = 0.0f;

    const int a_r  = tid >> 3;
    const int a_k  = (tid & 7) * 4;
    const int b_n  = lane * 4;

    for (int k0 = 0; k0 < HIDN; k0 += 32) {
        #pragma unroll
        for (int p = 0; p < 4; p++) {
            int r = a_r + p * 32;
            float4 v = *(const float4*)&X[(m0 + r) * HIDN + k0 + a_k];
            v.x = to_tf32(v.x); v.y = to_tf32(v.y);
            v.z = to_tf32(v.z); v.w = to_tf32(v.w);
            *(float4*)&As[r][a_k] = v;
        }
        #pragma unroll
        for (int p = 0; p < 4; p++) {
            int kk = warp + p * 8;
            float4 v = *(const float4*)&W[(k0 + kk) * HIDN + ncol0 + b_n];
            v.x = to_tf32(v.x); v.y = to_tf32(v.y);
            v.z = to_tf32(v.z); v.w = to_tf32(v.w);
            *(float4*)&Bs[kk][b_n] = v;
        }
        __syncthreads();

        #pragma unroll
        for (int kc = 0; kc < 4; kc++) {
            const int kr = kc * 8;
            float a[4][4];
            #pragma unroll
            for (int mt = 0; mt < 4; mt++) {
                int mr = wm + mt * 16;
                a[mt][0] = As[mr + g    ][kr + t4    ];
                a[mt][1] = As[mr + g + 8][kr + t4    ];
                a[mt][2] = As[mr + g    ][kr + t4 + 4];
                a[mt][3] = As[mr + g + 8][kr + t4 + 4];
            }
            #pragma unroll
            for (int nt = 0; nt < 4; nt++) {
                float b0 = Bs[kr + t4    ][wn + nt * 8 + g];
                float b1 = Bs[kr + t4 + 4][wn + nt * 8 + g];
                #pragma unroll
                for (int mt = 0; mt < 4; mt++)
                    mma_tf32(acc[mt][nt], a[mt], b0, b1);
            }
        }
        __syncthreads();
    }

    #pragma unroll
    for (int mt = 0; mt < 4; mt++) {
        #pragma unroll
        for (int nt = 0; nt < 4; nt++) {
            int col = ncol0 + wn + nt * 8 + t4 * 2;
            int h = col >> 6;
            int d = col & 63;
            float bi0 = bias[col];
            float bi1 = bias[col + 1];
            #pragma unroll
            for (int rh = 0; rh < 2; rh++) {
                int m = m0 + wm + mt * 16 + g + rh * 8;
                int b = m >> 11;
                int s = m & 2047;
                float2 v;
                v.x = acc[mt][nt][rh * 2 + 0] + bi0;
                v.y = acc[mt][nt][rh * 2 + 1] + bi1;
                *(float2*)&Out[(((b * NH + h) * SS) + s) * HD + d] = v;
            }
        }
    }
}

// ---------------------------------------------------------------------------
// RoPE (+ query scaling)
// ---------------------------------------------------------------------------
__global__ __launch_bounds__(256) void rope_kernel() {
    int idx = blockIdx.x * blockDim.x + threadIdx.x;
    int j  = idx & 31;
    int s  = (idx >> 5) & (SS - 1);
    int bh = idx >> 16;
    float c  = g_cos[(s << 5) + j];
    float sn = g_sin[(s << 5) + j];
    int base = (bh * SS + s) * HD;
    const float scale = 0.125f;

    float q1 = g_Q[base + j], q2 = g_Q[base + j + 32];
    g_Q[base + j]      = (q1 * c - q2 * sn) * scale;
    g_Q[base + j + 32] = (q2 * c + q1 * sn) * scale;

    float k1 = g_K[base + j], k2 = g_K[base + j + 32];
    g_K[base + j]      = k1 * c - k2 * sn;
    g_K[base + j + 32] = k2 * c + k1 * sn;
}

// ---------------------------------------------------------------------------
// Flash attention with tf32 tensor cores.
// 128 threads = 4 warps; warp w owns q-rows [wm, wm+16); BQ=64, BKV=32, D=64.
// QK^T and PV both via mma.sync.m16n8k8.tf32.
// ---------------------------------------------------------------------------
__global__ __launch_bounds__(128) void attn_tf32(
    const float* __restrict__ mask, float* __restrict__ out)
{
    __shared__ float Qs[64][68];   // staging for Q fragments (bank: 4g+t4)
    __shared__ float Ks[32][68];   // B-frag bank: 4g+t4
    __shared__ float Vs[32][72];   // B-frag bank: 8t4+g
    __shared__ float Ps[64][36];   // A-frag bank: 4g+t4 (warp-private rows)
    __shared__ float Ms[32];       // mask slice

    const int bh = blockIdx.y;
    const int b  = bh / NH;
    const int h  = bh % NH;
    const int q0 = blockIdx.x * 64;

    const float* Qb = g_Q + (size_t)bh * SS * HD;
    const float* Kb = g_K + (size_t)bh * SS * HD;
    const float* Vb = g_V + (size_t)bh * SS * HD;
    const float* mk = mask + b * SS;

    const int tid  = threadIdx.x;
    const int lane = tid & 31;
    const int warp = tid >> 5;
    const int g    = lane >> 2;
    const int t4   = lane & 3;
    const int wm   = warp * 16;

    // Stage Q (tf32) and hoist fragments to registers
    for (int i = tid; i < 1024; i += 128) {
        int r = i >> 4, c = (i & 15) << 2;
        float4 v = *(const float4*)&Qb[(q0 + r) * HD + c];
        v.x = to_tf32(v.x); v.y = to_tf32(v.y);
        v.z = to_tf32(v.z); v.w = to_tf32(v.w);
        *(float4*)&Qs[r][c] = v;
    }
    __syncthreads();

    float qf[8][4];
    #pragma unroll
    for (int kc = 0; kc < 8; kc++) {
        int kr = kc * 8;
        qf[kc][0] = Qs[wm + g    ][kr + t4    ];
        qf[kc][1] = Qs[wm + g + 8][kr + t4    ];
        qf[kc][2] = Qs[wm + g    ][kr + t4 + 4];
        qf[kc][3] = Qs[wm + g + 8][kr + t4 + 4];
    }

    float oacc[8][4];
    #pragma unroll
    for (int dt = 0; dt < 8; dt++)
        #pragma unroll
        for (int i = 0; i < 4; i++) oacc[dt][i] = 0.0f;
    float m0r = -1e30f, m1r = -1e30f, l0 = 0.0f, l1 = 0.0f;

    for (int k0 = 0; k0 < SS; k0 += 32) {
        __syncthreads();   // protect Ks/Vs/Ms from previous iteration reads
        for (int i = tid; i < 512; i += 128) {
            int r = i >> 4, c = (i & 15) << 2;
            float4 kv = *(const float4*)&Kb[(k0 + r) * HD + c];
            kv.x = to_tf32(kv.x); kv.y = to_tf32(kv.y);
            kv.z = to_tf32(kv.z); kv.w = to_tf32(kv.w);
            *(float4*)&Ks[r][c] = kv;
            float4 vv = *(const float4*)&Vb[(k0 + r) * HD + c];
            vv.x = to_tf32(vv.x); vv.y = to_tf32(vv.y);
            vv.z = to_tf32(vv.z); vv.w = to_tf32(vv.w);
            *(float4*)&Vs[r][c] = vv;
        }
        if (tid < 32) Ms[tid] = mk[k0 + tid];
        __syncthreads();

        // ---- S = Q @ K^T  (m16 x n32 per warp) ----
        float sc[4][4];
        #pragma unroll
        for (int nt = 0; nt < 4; nt++)
            #pragma unroll
            for (int i = 0; i < 4; i++) sc[nt][i] = 0.0f;

        #pragma unroll
        for (int kc = 0; kc < 8; kc++) {
            int kr = kc * 8;
            #pragma unroll
            for (int nt = 0; nt < 4; nt++) {
                float b0 = Ks[nt * 8 + g][kr + t4    ];
                float b1 = Ks[nt * 8 + g][kr + t4 + 4];
                mma_tf32(sc[nt], qf[kc], b0, b1);
            }
        }

        // ---- mask + online softmax (rows g and g+8 of this warp's m16) ----
        #pragma unroll
        for (int nt = 0; nt < 4; nt++) {
            float mv0 = Ms[nt * 8 + 2 * t4    ];
            float mv1 = Ms[nt * 8 + 2 * t4 + 1];
            sc[nt][0] += mv0; sc[nt][1] += mv1;
            sc[nt][2] += mv0; sc[nt][3] += mv1;
        }
        float rx0 = -1e30f, rx1 = -1e30f;
        #pragma unroll
        for (int nt = 0; nt < 4; nt++) {
            rx0 = fmaxf(rx0, fmaxf(sc[nt][0], sc[nt][1]));
            rx1 = fmaxf(rx1, fmaxf(sc[nt][2], sc[nt][3]));
        }
        rx0 = fmaxf(rx0, __shfl_xor_sync(0xffffffffu, rx0, 1));
        rx0 = fmaxf(rx0, __shfl_xor_sync(0xffffffffu, rx0, 2));
        rx1 = fmaxf(rx1, __shfl_xor_sync(0xffffffffu, rx1, 1));
        rx1 = fmaxf(rx1, __shfl_xor_sync(0xffffffffu, rx1, 2));

        float m0n = fmaxf(m0r, rx0);
        float m1n = fmaxf(m1r, rx1);
        float c0 = __expf(m0r - m0n);
        float c1 = __expf(m1r - m1n);
        m0r = m0n; m1r = m1n;

        float rs0 = 0.0f, rs1 = 0.0f;
        #pragma unroll
        for (int nt = 0; nt < 4; nt++) {
            float p0 = to_tf32(__expf(sc[nt][0] - m0n));
            float p1 = to_tf32(__expf(sc[nt][1] - m0n));
            float p2 = to_tf32(__expf(sc[nt][2] - m1n));
            float p3 = to_tf32(__expf(sc[nt][3] - m1n));
            rs0 += p0 + p1;
            rs1 += p2 + p3;
            *(float2*)&Ps[wm + g    ][nt * 8 + 2 * t4] = make_float2(p0, p1);
            *(float2*)&Ps[wm + g + 8][nt * 8 + 2 * t4] = make_float2(p2, p3);
        }
        rs0 += __shfl_xor_sync(0xffffffffu, rs0, 1);
        rs0 += __shfl_xor_sync(0xffffffffu, rs0, 2);
        rs1 += __shfl_xor_sync(0xffffffffu, rs1, 1);
        rs1 += __shfl_xor_sync(0xffffffffu, rs1, 2);
        l0 = l0 * c0 + rs0;
        l1 = l1 * c1 + rs1;

        #pragma unroll
        for (int dt = 0; dt < 8; dt++) {
            oacc[dt][0] *= c0; oacc[dt][1] *= c0;
            oacc[dt][2] *= c1; oacc[dt][3] *= c1;
        }
        __syncwarp();   // Ps is warp-private; make stores visible to lanes

        // ---- O += P @ V  (m16 x n64, k32) ----
        #pragma unroll
        for (int kc = 0; kc < 4; kc++) {
            int kr = kc * 8;
            float pa[4];
            pa[0] = Ps[wm + g    ][kr + t4    ];
            pa[1] = Ps[wm + g + 8][kr + t4    ];
            pa[2] = Ps[wm + g    ][kr + t4 + 4];
            pa[3] = Ps[wm + g + 8][kr + t4 + 4];
            #pragma unroll
            for (int dt = 0; dt < 8; dt++) {
                float b0 = Vs[kr + t4    ][dt * 8 + g];
                float b1 = Vs[kr + t4 + 4][dt * 8 + g];
                mma_tf32(oacc[dt], pa, b0, b1);
            }
        }
    }

    // ---- normalize + write out [B, S, H*D] ----
    float inv0 = 1.0f / l0;
    float inv1 = 1.0f / l1;
    int r0 = q0 + wm + g;
    int r1 = r0 + 8;
    #pragma unroll
    for (int dt = 0; dt < 8; dt++) {
        int d = dt * 8 + 2 * t4;
        float2 v0 = make_float2(oacc[dt][0] * inv0, oacc[dt][1] * inv0);
        float2 v1 = make_float2(oacc[dt][2] * inv1, oacc[dt][3] * inv1);
        *(float2*)&out[(b * SS + r0) * HIDN + h * HD + d] = v0;
        *(float2*)&out[(b * SS + r1) * HIDN + h * HD + d] = v1;
    }
}

// ---------------------------------------------------------------------------
extern "C" void kernel_launch(void* const* d_in, const int* in_sizes, int n_in,
                              void* d_out, int out_size) {
    const float* hs   = (const float*)d_in[0];
    const float* mask = (const float*)d_in[1];
    const float* Wq   = (const float*)d_in[2];
    const float* bq   = (const float*)d_in[3];
    const float* Wk   = (const float*)d_in[4];
    const float* bk   = (const float*)d_in[5];
    const float* Wv   = (const float*)d_in[6];
    const float* bv   = (const float*)d_in[7];
    float* out = (float*)d_out;

    sincos_kernel<<<(SS * 32 + 255) / 256, 256>>>();
    qkv_gemm_tf32<<<dim3(30, 32), 256>>>(hs, Wq, bq, Wk, bk, Wv, bv);
    rope_kernel<<<(BB * NH * SS * 32) / 256, 256>>>();
    attn_tf32<<<dim3(SS / 64, BB * NH), 128>>>(mask, out);
}

// round 6
// speedup vs baseline: 3.4367x; 1.2318x over previous
#include <cuda_runtime.h>
#include <cstdint>
#include <math.h>

#define BB 2
#define SS 2048
#define HIDN 1280
#define NH 20
#define HD 64

// Scratch (alloc-free rule: __device__ globals)
__device__ float g_Q[BB*NH*SS*HD];
__device__ float g_K[BB*NH*SS*HD];
__device__ float g_V[BB*NH*SS*HD];
__device__ float g_cos[SS*32];
__device__ float g_sin[SS*32];

// ---------------------------------------------------------------------------
// RoPE cos/sin table
// ---------------------------------------------------------------------------
__global__ void sincos_kernel() {
    int idx = blockIdx.x * blockDim.x + threadIdx.x;
    if (idx >= SS * 32) return;
    int j = idx & 31;
    int s = idx >> 5;
    double invf = exp(-((double)j / 32.0) * log(10000.0));
    double a = (double)s * invf;
    g_cos[idx] = (float)cos(a);
    g_sin[idx] = (float)sin(a);
}

// ---------------------------------------------------------------------------
// tf32 helpers
// ---------------------------------------------------------------------------
__device__ __forceinline__ float to_tf32(float x) {
    float r;
    asm("cvt.rna.tf32.f32 %0, %1;" : "=f"(r) : "f"(x));
    return r;
}

__device__ __forceinline__ void mma_tf32(float c[4], const float a[4],
                                         float b0, float b1) {
    asm volatile(
        "mma.sync.aligned.m16n8k8.row.col.f32.tf32.tf32.f32 "
        "{%0,%1,%2,%3}, {%4,%5,%6,%7}, {%8,%9}, {%0,%1,%2,%3};"
        : "+f"(c[0]), "+f"(c[1]), "+f"(c[2]), "+f"(c[3])
        : "r"(__float_as_uint(a[0])), "r"(__float_as_uint(a[1])),
          "r"(__float_as_uint(a[2])), "r"(__float_as_uint(a[3])),
          "r"(__float_as_uint(b0)),  "r"(__float_as_uint(b1)));
}

__device__ __forceinline__ void cp16(unsigned int dst, const void* src) {
    asm volatile("cp.async.cg.shared.global [%0], [%1], 16;\n"
                 :: "r"(dst), "l"(src));
}
__device__ __forceinline__ void cp_commit() {
    asm volatile("cp.async.commit_group;\n" ::: "memory");
}
template <int N>
__device__ __forceinline__ void cp_wait() {
    asm volatile("cp.async.wait_group %0;\n" :: "n"(N) : "memory");
}

// ---------------------------------------------------------------------------
// Fused QKV projection GEMM — tf32 tensor cores (unchanged from R2/R3).
// ---------------------------------------------------------------------------
__global__ __launch_bounds__(256, 2) void qkv_gemm_tf32(
    const float* __restrict__ X,
    const float* __restrict__ Wq, const float* __restrict__ bq,
    const float* __restrict__ Wk, const float* __restrict__ bk,
    const float* __restrict__ Wv, const float* __restrict__ bv)
{
    __shared__ float As[128][36];
    __shared__ float Bs[32][136];

    const int n0g   = blockIdx.x * 128;
    const int m0    = blockIdx.y * 128;
    const int which = n0g / HIDN;
    const int ncol0 = n0g % HIDN;

    const float* W    = (which == 0) ? Wq : (which == 1 ? Wk : Wv);
    const float* bias = (which == 0) ? bq : (which == 1 ? bk : bv);
    float*       Out  = (which == 0) ? g_Q : (which == 1 ? g_K : g_V);

    const int tid  = threadIdx.x;
    const int lane = tid & 31;
    const int warp = tid >> 5;
    const int wm   = (warp & 1) * 64;
    const int wn   = (warp >> 1) * 32;
    const int g    = lane >> 2;
    const int t4   = lane & 3;

    float acc[4][4][4];
    #pragma unroll
    for (int mt = 0; mt < 4; mt++)
        #pragma unroll
        for (int nt = 0; nt < 4; nt++)
            #pragma unroll
            for (int i = 0; i < 4; i++) acc[mt][nt][i] = 0.0f;

    const int a_r  = tid >> 3;
    const int a_k  = (tid & 7) * 4;
    const int b_n  = lane * 4;

    for (int k0 = 0; k0 < HIDN; k0 += 32) {
        #pragma unroll
        for (int p = 0; p < 4; p++) {
            int r = a_r + p * 32;
            float4 v = *(const float4*)&X[(m0 + r) * HIDN + k0 + a_k];
            v.x = to_tf32(v.x); v.y = to_tf32(v.y);
            v.z = to_tf32(v.z); v.w = to_tf32(v.w);
            *(float4*)&As[r][a_k] = v;
        }
        #pragma unroll
        for (int p = 0; p < 4; p++) {
            int kk = warp + p * 8;
            float4 v = *(const float4*)&W[(k0 + kk) * HIDN + ncol0 + b_n];
            v.x = to_tf32(v.x); v.y = to_tf32(v.y);
            v.z = to_tf32(v.z); v.w = to_tf32(v.w);
            *(float4*)&Bs[kk][b_n] = v;
        }
        __syncthreads();

        #pragma unroll
        for (int kc = 0; kc < 4; kc++) {
            const int kr = kc * 8;
            float a[4][4];
            #pragma unroll
            for (int mt = 0; mt < 4; mt++) {
                int mr = wm + mt * 16;
                a[mt][0] = As[mr + g    ][kr + t4    ];
                a[mt][1] = As[mr + g + 8][kr + t4    ];
                a[mt][2] = As[mr + g    ][kr + t4 + 4];
                a[mt][3] = As[mr + g + 8][kr + t4 + 4];
            }
            #pragma unroll
            for (int nt = 0; nt < 4; nt++) {
                float b0 = Bs[kr + t4    ][wn + nt * 8 + g];
                float b1 = Bs[kr + t4 + 4][wn + nt * 8 + g];
                #pragma unroll
                for (int mt = 0; mt < 4; mt++)
                    mma_tf32(acc[mt][nt], a[mt], b0, b1);
            }
        }
        __syncthreads();
    }

    #pragma unroll
    for (int mt = 0; mt < 4; mt++) {
        #pragma unroll
        for (int nt = 0; nt < 4; nt++) {
            int col = ncol0 + wn + nt * 8 + t4 * 2;
            int h = col >> 6;
            int d = col & 63;
            float bi0 = bias[col];
            float bi1 = bias[col + 1];
            #pragma unroll
            for (int rh = 0; rh < 2; rh++) {
                int m = m0 + wm + mt * 16 + g + rh * 8;
                int b = m >> 11;
                int s = m & 2047;
                float2 v;
                v.x = acc[mt][nt][rh * 2 + 0] + bi0;
                v.y = acc[mt][nt][rh * 2 + 1] + bi1;
                *(float2*)&Out[(((b * NH + h) * SS) + s) * HD + d] = v;
            }
        }
    }
}

// ---------------------------------------------------------------------------
// RoPE (+ query scaling). Also pre-rounds Q, K, V to tf32 so the attention
// kernel can stage raw bytes with cp.async (no cvt at staging).
// ---------------------------------------------------------------------------
__global__ __launch_bounds__(256) void rope_kernel() {
    int idx = blockIdx.x * blockDim.x + threadIdx.x;
    int j  = idx & 31;
    int s  = (idx >> 5) & (SS - 1);
    int bh = idx >> 16;
    float c  = g_cos[(s << 5) + j];
    float sn = g_sin[(s << 5) + j];
    int base = (bh * SS + s) * HD;
    const float scale = 0.125f;

    float q1 = g_Q[base + j], q2 = g_Q[base + j + 32];
    g_Q[base + j]      = to_tf32((q1 * c - q2 * sn) * scale);
    g_Q[base + j + 32] = to_tf32((q2 * c + q1 * sn) * scale);

    float k1 = g_K[base + j], k2 = g_K[base + j + 32];
    g_K[base + j]      = to_tf32(k1 * c - k2 * sn);
    g_K[base + j + 32] = to_tf32(k2 * c + k1 * sn);

    g_V[base + j]      = to_tf32(g_V[base + j]);
    g_V[base + j + 32] = to_tf32(g_V[base + j + 32]);
}

// ---------------------------------------------------------------------------
// Flash attention, tf32 mma, cp.async double-buffered K/V.
// 128 threads = 4 warps; warp w owns q-rows [16w, 16w+16); BQ=64, BKV=32.
// Dynamic smem layout (floats):
//   [0,     4352)  Qs[64][68] staging, reused as Ps[64][36] after hoist
//   [4352,  6528)  K buf0 [32][68]
//   [6528,  8704)  K buf1 [32][68]
//   [8704, 11008)  V buf0 [32][72]
//   [11008,13312)  V buf1 [32][72]
// ---------------------------------------------------------------------------
#define OFF_K0 4352
#define OFF_V0 8704
#define KBUF 2176
#define VBUF 2304
#define ATTN_SMEM_BYTES (13312 * 4)

__global__ __launch_bounds__(128) void attn_tf32(
    const float* __restrict__ mask, float* __restrict__ out)
{
    extern __shared__ float sm[];
    float (*Ps)[36] = (float(*)[36])sm;

    const int bh = blockIdx.y;
    const int b  = bh / NH;
    const int h  = bh % NH;
    const int q0 = blockIdx.x * 64;

    const float* Qb = g_Q + (size_t)bh * SS * HD;
    const float* Kb = g_K + (size_t)bh * SS * HD;
    const float* Vb = g_V + (size_t)bh * SS * HD;
    const float2* mk2 = (const float2*)(mask + b * SS);

    const int tid  = threadIdx.x;
    const int lane = tid & 31;
    const int warp = tid >> 5;
    const int g    = lane >> 2;
    const int t4   = lane & 3;
    const int wm   = warp * 16;

    const unsigned int sbase = (unsigned int)__cvta_generic_to_shared(sm);
    const int c_row = tid >> 2;          // 0..31
    const int c_c4  = (tid & 3) << 2;    // 0,4,8,12 (+16p covers all 64 cols)

    // Prologue: kick off tile 0 K/V copies (full 32x64 tiles: 4 cp16/thread each)
    {
        #pragma unroll
        for (int p = 0; p < 4; p++) {
            int c = c_c4 + p * 16;
            cp16(sbase + (OFF_K0 + c_row * 68 + c) * 4, Kb + c_row * HD + c);
            cp16(sbase + (OFF_V0 + c_row * 72 + c) * 4, Vb + c_row * HD + c);
        }
        cp_commit();
    }

    // Stage Q (already tf32-rounded by rope kernel)
    for (int i = tid; i < 1024; i += 128) {
        int r = i >> 4, c = (i & 15) << 2;
        *(float4*)&sm[r * 68 + c] = *(const float4*)&Qb[(q0 + r) * HD + c];
    }
    __syncthreads();

    // Hoist Q fragments
    float qf[8][4];
    #pragma unroll
    for (int kc = 0; kc < 8; kc++) {
        int kr = kc * 8;
        qf[kc][0] = sm[(wm + g    ) * 68 + kr + t4    ];
        qf[kc][1] = sm[(wm + g + 8) * 68 + kr + t4    ];
        qf[kc][2] = sm[(wm + g    ) * 68 + kr + t4 + 4];
        qf[kc][3] = sm[(wm + g + 8) * 68 + kr + t4 + 4];
    }

    float oacc[8][4];
    #pragma unroll
    for (int dt = 0; dt < 8; dt++)
        #pragma unroll
        for (int i = 0; i < 4; i++) oacc[dt][i] = 0.0f;
    float m0r = -1e30f, m1r = -1e30f, l0 = 0.0f, l1 = 0.0f;

    for (int it = 0; it < SS / 32; it++) {
        const int buf = it & 1;
        // Issue next tile's copies (into the other buffer) and wait for current
        if (it < SS / 32 - 1) {
            const float* Kn = Kb + (it + 1) * 32 * HD;
            const float* Vn = Vb + (it + 1) * 32 * HD;
            int ko = OFF_K0 + (buf ^ 1) * KBUF;
            int vo = OFF_V0 + (buf ^ 1) * VBUF;
            #pragma unroll
            for (int p = 0; p < 4; p++) {
                int c = c_c4 + p * 16;
                cp16(sbase + (ko + c_row * 68 + c) * 4, Kn + c_row * HD + c);
                cp16(sbase + (vo + c_row * 72 + c) * 4, Vn + c_row * HD + c);
            }
            cp_commit();
            cp_wait<1>();
        } else {
            cp_wait<0>();
        }
        __syncthreads();   // current buffer visible to all warps

        const float* Kt = sm + OFF_K0 + buf * KBUF;
        const float* Vt = sm + OFF_V0 + buf * VBUF;

        // ---- S = Q @ K^T (m16 x n32 per warp) ----
        float sc[4][4];
        #pragma unroll
        for (int nt = 0; nt < 4; nt++)
            #pragma unroll
            for (int i = 0; i < 4; i++) sc[nt][i] = 0.0f;

        #pragma unroll
        for (int kc = 0; kc < 8; kc++) {
            int kr = kc * 8;
            #pragma unroll
            for (int nt = 0; nt < 4; nt++) {
                float b0 = Kt[(nt * 8 + g) * 68 + kr + t4    ];
                float b1 = Kt[(nt * 8 + g) * 68 + kr + t4 + 4];
                mma_tf32(sc[nt], qf[kc], b0, b1);
            }
        }

        // ---- mask + online softmax ----
        const int k0 = it * 32;
        #pragma unroll
        for (int nt = 0; nt < 4; nt++) {
            float2 mv = __ldg(&mk2[(k0 + nt * 8) / 2 + t4]);
            sc[nt][0] += mv.x; sc[nt][1] += mv.y;
            sc[nt][2] += mv.x; sc[nt][3] += mv.y;
        }
        float rx0 = -1e30f, rx1 = -1e30f;
        #pragma unroll
        for (int nt = 0; nt < 4; nt++) {
            rx0 = fmaxf(rx0, fmaxf(sc[nt][0], sc[nt][1]));
            rx1 = fmaxf(rx1, fmaxf(sc[nt][2], sc[nt][3]));
        }
        rx0 = fmaxf(rx0, __shfl_xor_sync(0xffffffffu, rx0, 1));
        rx0 = fmaxf(rx0, __shfl_xor_sync(0xffffffffu, rx0, 2));
        rx1 = fmaxf(rx1, __shfl_xor_sync(0xffffffffu, rx1, 1));
        rx1 = fmaxf(rx1, __shfl_xor_sync(0xffffffffu, rx1, 2));

        float m0n = fmaxf(m0r, rx0);
        float m1n = fmaxf(m1r, rx1);
        float c0 = __expf(m0r - m0n);
        float c1 = __expf(m1r - m1n);
        m0r = m0n; m1r = m1n;

        float rs0 = 0.0f, rs1 = 0.0f;
        #pragma unroll
        for (int nt = 0; nt < 4; nt++) {
            float p0 = to_tf32(__expf(sc[nt][0] - m0n));
            float p1 = to_tf32(__expf(sc[nt][1] - m0n));
            float p2 = to_tf32(__expf(sc[nt][2] - m1n));
            float p3 = to_tf32(__expf(sc[nt][3] - m1n));
            rs0 += p0 + p1;
            rs1 += p2 + p3;
            *(float2*)&Ps[wm + g    ][nt * 8 + 2 * t4] = make_float2(p0, p1);
            *(float2*)&Ps[wm + g + 8][nt * 8 + 2 * t4] = make_float2(p2, p3);
        }
        rs0 += __shfl_xor_sync(0xffffffffu, rs0, 1);
        rs0 += __shfl_xor_sync(0xffffffffu, rs0, 2);
        rs1 += __shfl_xor_sync(0xffffffffu, rs1, 1);
        rs1 += __shfl_xor_sync(0xffffffffu, rs1, 2);
        l0 = l0 * c0 + rs0;
        l1 = l1 * c1 + rs1;

        #pragma unroll
        for (int dt = 0; dt < 8; dt++) {
            oacc[dt][0] *= c0; oacc[dt][1] *= c0;
            oacc[dt][2] *= c1; oacc[dt][3] *= c1;
        }
        __syncwarp();   // Ps rows are warp-private

        // ---- O += P @ V (m16 x n64, k32) ----
        #pragma unroll
        for (int kc = 0; kc < 4; kc++) {
            int kr = kc * 8;
            float pa[4];
            pa[0] = Ps[wm + g    ][kr + t4    ];
            pa[1] = Ps[wm + g + 8][kr + t4    ];
            pa[2] = Ps[wm + g    ][kr + t4 + 4];
            pa[3] = Ps[wm + g + 8][kr + t4 + 4];
            #pragma unroll
            for (int dt = 0; dt < 8; dt++) {
                float b0 = Vt[(kr + t4    ) * 72 + dt * 8 + g];
                float b1 = Vt[(kr + t4 + 4) * 72 + dt * 8 + g];
                mma_tf32(oacc[dt], pa, b0, b1);
            }
        }
        __syncthreads();   // all warps done reading buf before it's overwritten
    }

    // ---- normalize + write out [B, S, H*D] ----
    float inv0 = 1.0f / l0;
    float inv1 = 1.0f / l1;
    int r0 = q0 + wm + g;
    int r1 = r0 + 8;
    #pragma unroll
    for (int dt = 0; dt < 8; dt++) {
        int d = dt * 8 + 2 * t4;
        float2 v0 = make_float2(oacc[dt][0] * inv0, oacc[dt][1] * inv0);
        float2 v1 = make_float2(oacc[dt][2] * inv1, oacc[dt][3] * inv1);
        *(float2*)&out[(b * SS + r0) * HIDN + h * HD + d] = v0;
        *(float2*)&out[(b * SS + r1) * HIDN + h * HD + d] = v1;
    }
}

// ---------------------------------------------------------------------------
extern "C" void kernel_launch(void* const* d_in, const int* in_sizes, int n_in,
                              void* d_out, int out_size) {
    const float* hs   = (const float*)d_in[0];
    const float* mask = (const float*)d_in[1];
    const float* Wq   = (const float*)d_in[2];
    const float* bq   = (const float*)d_in[3];
    const float* Wk   = (const float*)d_in[4];
    const float* bk   = (const float*)d_in[5];
    const float* Wv   = (const float*)d_in[6];
    const float* bv   = (const float*)d_in[7];
    float* out = (float*)d_out;

    static bool attr_set = false;
    if (!attr_set) {
        cudaFuncSetAttribute(attn_tf32,
                             cudaFuncAttributeMaxDynamicSharedMemorySize,
                             ATTN_SMEM_BYTES);
        attr_set = true;
    }

    sincos_kernel<<<(SS * 32 + 255) / 256, 256>>>();
    qkv_gemm_tf32<<<dim3(30, 32), 256>>>(hs, Wq, bq, Wk, bk, Wv, bv);
    rope_kernel<<<(BB * NH * SS * 32) / 256, 256>>>();
    attn_tf32<<<dim3(SS / 64, BB * NH), 128, ATTN_SMEM_BYTES>>>(mask, out);
}

// round 7
// speedup vs baseline: 3.6049x; 1.0489x over previous
#include <cuda_runtime.h>
#include <cstdint>
#include <math.h>

#define BB 2
#define SS 2048
#define HIDN 1280
#define NH 20
#define HD 64

// Scratch (alloc-free rule: __device__ globals)
__device__ float g_Q[BB*NH*SS*HD];
__device__ float g_K[BB*NH*SS*HD];
__device__ float g_V[BB*NH*SS*HD];
__device__ float g_X[BB*SS*HIDN];      // tf32-rounded hidden states
__device__ float g_W[3*HIDN*HIDN];     // tf32-rounded Wq|Wk|Wv
__device__ float g_cos[SS*32];
__device__ float g_sin[SS*32];

// ---------------------------------------------------------------------------
// RoPE cos/sin table
// ---------------------------------------------------------------------------
__global__ void sincos_kernel() {
    int idx = blockIdx.x * blockDim.x + threadIdx.x;
    if (idx >= SS * 32) return;
    int j = idx & 31;
    int s = idx >> 5;
    double invf = exp(-((double)j / 32.0) * log(10000.0));
    double a = (double)s * invf;
    g_cos[idx] = (float)cos(a);
    g_sin[idx] = (float)sin(a);
}

// ---------------------------------------------------------------------------
// tf32 helpers
// ---------------------------------------------------------------------------
__device__ __forceinline__ float to_tf32(float x) {
    float r;
    asm("cvt.rna.tf32.f32 %0, %1;" : "=f"(r) : "f"(x));
    return r;
}

__device__ __forceinline__ void mma_tf32(float c[4], const float a[4],
                                         float b0, float b1) {
    asm volatile(
        "mma.sync.aligned.m16n8k8.row.col.f32.tf32.tf32.f32 "
        "{%0,%1,%2,%3}, {%4,%5,%6,%7}, {%8,%9}, {%0,%1,%2,%3};"
        : "+f"(c[0]), "+f"(c[1]), "+f"(c[2]), "+f"(c[3])
        : "r"(__float_as_uint(a[0])), "r"(__float_as_uint(a[1])),
          "r"(__float_as_uint(a[2])), "r"(__float_as_uint(a[3])),
          "r"(__float_as_uint(b0)),  "r"(__float_as_uint(b1)));
}

__device__ __forceinline__ void cp16(unsigned int dst, const void* src) {
    asm volatile("cp.async.cg.shared.global [%0], [%1], 16;\n"
                 :: "r"(dst), "l"(src));
}
__device__ __forceinline__ void cp_commit() {
    asm volatile("cp.async.commit_group;\n" ::: "memory");
}
template <int N>
__device__ __forceinline__ void cp_wait() {
    asm volatile("cp.async.wait_group %0;\n" :: "n"(N) : "memory");
}

// ---------------------------------------------------------------------------
// Prep: round X and the 3 weight matrices to tf32 (rna) into scratch so the
// GEMM can stage with raw cp.async copies.
// ---------------------------------------------------------------------------
#define NX4 (BB*SS*HIDN/4)
#define NW4 (HIDN*HIDN/4)

__global__ __launch_bounds__(256) void prep_tf32(
    const float4* __restrict__ X,
    const float4* __restrict__ Wq,
    const float4* __restrict__ Wk,
    const float4* __restrict__ Wv)
{
    int i = blockIdx.x * blockDim.x + threadIdx.x;
    float4 v;
    float4* dst;
    if (i < NX4) {
        v = X[i]; dst = ((float4*)g_X) + i;
    } else if (i < NX4 + NW4) {
        int j = i - NX4; v = Wq[j]; dst = ((float4*)g_W) + j;
    } else if (i < NX4 + 2 * NW4) {
        int j = i - NX4 - NW4; v = Wk[j]; dst = ((float4*)g_W) + NW4 + j;
    } else {
        int j = i - NX4 - 2 * NW4; v = Wv[j]; dst = ((float4*)g_W) + 2 * NW4 + j;
    }
    v.x = to_tf32(v.x); v.y = to_tf32(v.y);
    v.z = to_tf32(v.z); v.w = to_tf32(v.w);
    *dst = v;
}

// ---------------------------------------------------------------------------
// Fused QKV projection GEMM — tf32 mma + cp.async 2-stage pipeline.
// Dynamic smem (floats): As0 [0,4608) As1 [4608,9216)  ([128][36])
//                        Bs0 [9216,13568) Bs1 [13568,17920)  ([32][136])
// ---------------------------------------------------------------------------
#define QAS 4608
#define QBS 4352
#define QKV_SMEM_BYTES (17920 * 4)

__global__ __launch_bounds__(256, 2) void qkv_gemm_tf32(
    const float* __restrict__ bq,
    const float* __restrict__ bk,
    const float* __restrict__ bv)
{
    extern __shared__ float sm[];

    const int n0g   = blockIdx.x * 128;
    const int m0    = blockIdx.y * 128;
    const int which = n0g / HIDN;
    const int ncol0 = n0g % HIDN;

    const float* Wp   = g_W + (size_t)which * HIDN * HIDN;
    const float* bias = (which == 0) ? bq : (which == 1 ? bk : bv);
    float*       Out  = (which == 0) ? g_Q : (which == 1 ? g_K : g_V);

    const int tid  = threadIdx.x;
    const int lane = tid & 31;
    const int warp = tid >> 5;
    const int wm   = (warp & 1) * 64;
    const int wn   = (warp >> 1) * 32;
    const int g    = lane >> 2;
    const int t4   = lane & 3;

    const unsigned int sbase = (unsigned int)__cvta_generic_to_shared(sm);
    const int a_r  = tid >> 3;          // 0..31 (+32p)
    const int a_k  = (tid & 7) * 4;     // 0..28
    const int b_n  = lane * 4;          // 0..124

    float acc[4][4][4];
    #pragma unroll
    for (int mt = 0; mt < 4; mt++)
        #pragma unroll
        for (int nt = 0; nt < 4; nt++)
            #pragma unroll
            for (int i = 0; i < 4; i++) acc[mt][nt][i] = 0.0f;

    // Prologue: issue tile 0 into buffer 0
    {
        #pragma unroll
        for (int p = 0; p < 4; p++) {
            int r = a_r + 32 * p;
            cp16(sbase + (r * 36 + a_k) * 4, g_X + (m0 + r) * HIDN + a_k);
        }
        #pragma unroll
        for (int p = 0; p < 4; p++) {
            int kk = warp + 8 * p;
            cp16(sbase + (9216 + kk * 136 + b_n) * 4, Wp + kk * HIDN + ncol0 + b_n);
        }
        cp_commit();
    }

    for (int kt = 0; kt < HIDN / 32; kt++) {
        const int buf = kt & 1;
        cp_wait<0>();
        __syncthreads();   // tile visible + everyone done reading buf^1

        if (kt < HIDN / 32 - 1) {
            const int k0 = (kt + 1) * 32;
            const int ao = (buf ^ 1) * QAS;
            const int bo = 9216 + (buf ^ 1) * QBS;
            #pragma unroll
            for (int p = 0; p < 4; p++) {
                int r = a_r + 32 * p;
                cp16(sbase + (ao + r * 36 + a_k) * 4,
                     g_X + (m0 + r) * HIDN + k0 + a_k);
            }
            #pragma unroll
            for (int p = 0; p < 4; p++) {
                int kk = warp + 8 * p;
                cp16(sbase + (bo + kk * 136 + b_n) * 4,
                     Wp + (k0 + kk) * HIDN + ncol0 + b_n);
            }
            cp_commit();
        }

        const float* A  = sm + buf * QAS;
        const float* Bt = sm + 9216 + buf * QBS;

        #pragma unroll
        for (int kc = 0; kc < 4; kc++) {
            const int kr = kc * 8;
            float a[4][4];
            #pragma unroll
            for (int mt = 0; mt < 4; mt++) {
                int mr = wm + mt * 16;
                a[mt][0] = A[(mr + g    ) * 36 + kr + t4    ];
                a[mt][1] = A[(mr + g + 8) * 36 + kr + t4    ];
                a[mt][2] = A[(mr + g    ) * 36 + kr + t4 + 4];
                a[mt][3] = A[(mr + g + 8) * 36 + kr + t4 + 4];
            }
            #pragma unroll
            for (int nt = 0; nt < 4; nt++) {
                float b0 = Bt[(kr + t4    ) * 136 + wn + nt * 8 + g];
                float b1 = Bt[(kr + t4 + 4) * 136 + wn + nt * 8 + g];
                #pragma unroll
                for (int mt = 0; mt < 4; mt++)
                    mma_tf32(acc[mt][nt], a[mt], b0, b1);
            }
        }
    }

    // Epilogue: bias + scatter into [B, H, S, D]
    #pragma unroll
    for (int mt = 0; mt < 4; mt++) {
        #pragma unroll
        for (int nt = 0; nt < 4; nt++) {
            int col = ncol0 + wn + nt * 8 + t4 * 2;
            int h = col >> 6;
            int d = col & 63;
            float bi0 = bias[col];
            float bi1 = bias[col + 1];
            #pragma unroll
            for (int rh = 0; rh < 2; rh++) {
                int m = m0 + wm + mt * 16 + g + rh * 8;
                int b = m >> 11;
                int s = m & 2047;
                float2 v;
                v.x = acc[mt][nt][rh * 2 + 0] + bi0;
                v.y = acc[mt][nt][rh * 2 + 1] + bi1;
                *(float2*)&Out[(((b * NH + h) * SS) + s) * HD + d] = v;
            }
        }
    }
}

// ---------------------------------------------------------------------------
// RoPE (+ query scaling). Pre-rounds Q, K, V to tf32 for raw cp.async staging.
// ---------------------------------------------------------------------------
__global__ __launch_bounds__(256) void rope_kernel() {
    int idx = blockIdx.x * blockDim.x + threadIdx.x;
    int j  = idx & 31;
    int s  = (idx >> 5) & (SS - 1);
    int bh = idx >> 16;
    float c  = g_cos[(s << 5) + j];
    float sn = g_sin[(s << 5) + j];
    int base = (bh * SS + s) * HD;
    const float scale = 0.125f;

    float q1 = g_Q[base + j], q2 = g_Q[base + j + 32];
    g_Q[base + j]      = to_tf32((q1 * c - q2 * sn) * scale);
    g_Q[base + j + 32] = to_tf32((q2 * c + q1 * sn) * scale);

    float k1 = g_K[base + j], k2 = g_K[base + j + 32];
    g_K[base + j]      = to_tf32(k1 * c - k2 * sn);
    g_K[base + j + 32] = to_tf32(k2 * c + k1 * sn);

    g_V[base + j]      = to_tf32(g_V[base + j]);
    g_V[base + j + 32] = to_tf32(g_V[base + j + 32]);
}

// ---------------------------------------------------------------------------
// Flash attention, tf32 mma, cp.async double-buffered K/V, 1 barrier/iter.
// 128 threads = 4 warps; warp w owns q-rows [16w, 16w+16); BQ=64, BKV=32.
// Dynamic smem layout (floats):
//   [0,     4352)  Qs[64][68] staging, reused as Ps[64][36] after hoist
//   [4352,  6528)  K buf0 [32][68]
//   [6528,  8704)  K buf1 [32][68]
//   [8704, 11008)  V buf0 [32][72]
//   [11008,13312)  V buf1 [32][72]
// ---------------------------------------------------------------------------
#define OFF_K0 4352
#define OFF_V0 8704
#define KBUF 2176
#define VBUF 2304
#define ATTN_SMEM_BYTES (13312 * 4)

__global__ __launch_bounds__(128) void attn_tf32(
    const float* __restrict__ mask, float* __restrict__ out)
{
    extern __shared__ float sm[];
    float (*Ps)[36] = (float(*)[36])sm;

    const int bh = blockIdx.y;
    const int b  = bh / NH;
    const int h  = bh % NH;
    const int q0 = blockIdx.x * 64;

    const float* Qb = g_Q + (size_t)bh * SS * HD;
    const float* Kb = g_K + (size_t)bh * SS * HD;
    const float* Vb = g_V + (size_t)bh * SS * HD;
    const float2* mk2 = (const float2*)(mask + b * SS);

    const int tid  = threadIdx.x;
    const int lane = tid & 31;
    const int warp = tid >> 5;
    const int g    = lane >> 2;
    const int t4   = lane & 3;
    const int wm   = warp * 16;

    const unsigned int sbase = (unsigned int)__cvta_generic_to_shared(sm);
    const int c_row = tid >> 2;          // 0..31
    const int c_c4  = (tid & 3) << 2;    // 0,4,8,12 (+16p covers 64 cols)

    // Prologue: issue tile 0 K/V copies into buffer 0
    {
        #pragma unroll
        for (int p = 0; p < 4; p++) {
            int c = c_c4 + p * 16;
            cp16(sbase + (OFF_K0 + c_row * 68 + c) * 4, Kb + c_row * HD + c);
            cp16(sbase + (OFF_V0 + c_row * 72 + c) * 4, Vb + c_row * HD + c);
        }
        cp_commit();
    }

    // Stage Q (already tf32-rounded)
    for (int i = tid; i < 1024; i += 128) {
        int r = i >> 4, c = (i & 15) << 2;
        *(float4*)&sm[r * 68 + c] = *(const float4*)&Qb[(q0 + r) * HD + c];
    }
    __syncthreads();

    // Hoist Q fragments
    float qf[8][4];
    #pragma unroll
    for (int kc = 0; kc < 8; kc++) {
        int kr = kc * 8;
        qf[kc][0] = sm[(wm + g    ) * 68 + kr + t4    ];
        qf[kc][1] = sm[(wm + g + 8) * 68 + kr + t4    ];
        qf[kc][2] = sm[(wm + g    ) * 68 + kr + t4 + 4];
        qf[kc][3] = sm[(wm + g + 8) * 68 + kr + t4 + 4];
    }

    float oacc[8][4];
    #pragma unroll
    for (int dt = 0; dt < 8; dt++)
        #pragma unroll
        for (int i = 0; i < 4; i++) oacc[dt][i] = 0.0f;
    float m0r = -1e30f, m1r = -1e30f, l0 = 0.0f, l1 = 0.0f;

    for (int it = 0; it < SS / 32; it++) {
        const int buf = it & 1;
        cp_wait<0>();
        __syncthreads();   // buf visible + everyone done reading buf^1

        // Issue next tile into the other buffer, then compute (overlap)
        if (it < SS / 32 - 1) {
            const float* Kn = Kb + (it + 1) * 32 * HD;
            const float* Vn = Vb + (it + 1) * 32 * HD;
            int ko = OFF_K0 + (buf ^ 1) * KBUF;
            int vo = OFF_V0 + (buf ^ 1) * VBUF;
            #pragma unroll
            for (int p = 0; p < 4; p++) {
                int c = c_c4 + p * 16;
                cp16(sbase + (ko + c_row * 68 + c) * 4, Kn + c_row * HD + c);
                cp16(sbase + (vo + c_row * 72 + c) * 4, Vn + c_row * HD + c);
            }
            cp_commit();
        }

        const float* Kt = sm + OFF_K0 + buf * KBUF;
        const float* Vt = sm + OFF_V0 + buf * VBUF;

        // ---- S = Q @ K^T (m16 x n32 per warp) ----
        float sc[4][4];
        #pragma unroll
        for (int nt = 0; nt < 4; nt++)
            #pragma unroll
            for (int i = 0; i < 4; i++) sc[nt][i] = 0.0f;

        #pragma unroll
        for (int kc = 0; kc < 8; kc++) {
            int kr = kc * 8;
            #pragma unroll
            for (int nt = 0; nt < 4; nt++) {
                float b0 = Kt[(nt * 8 + g) * 68 + kr + t4    ];
                float b1 = Kt[(nt * 8 + g) * 68 + kr + t4 + 4];
                mma_tf32(sc[nt], qf[kc], b0, b1);
            }
        }

        // ---- mask + online softmax ----
        const int k0 = it * 32;
        #pragma unroll
        for (int nt = 0; nt < 4; nt++) {
            float2 mv = __ldg(&mk2[(k0 + nt * 8) / 2 + t4]);
            sc[nt][0] += mv.x; sc[nt][1] += mv.y;
            sc[nt][2] += mv.x; sc[nt][3] += mv.y;
        }
        float rx0 = -1e30f, rx1 = -1e30f;
        #pragma unroll
        for (int nt = 0; nt < 4; nt++) {
            rx0 = fmaxf(rx0, fmaxf(sc[nt][0], sc[nt][1]));
            rx1 = fmaxf(rx1, fmaxf(sc[nt][2], sc[nt][3]));
        }
        rx0 = fmaxf(rx0, __shfl_xor_sync(0xffffffffu, rx0, 1));
        rx0 = fmaxf(rx0, __shfl_xor_sync(0xffffffffu, rx0, 2));
        rx1 = fmaxf(rx1, __shfl_xor_sync(0xffffffffu, rx1, 1));
        rx1 = fmaxf(rx1, __shfl_xor_sync(0xffffffffu, rx1, 2));

        float m0n = fmaxf(m0r, rx0);
        float m1n = fmaxf(m1r, rx1);
        float c0 = __expf(m0r - m0n);
        float c1 = __expf(m1r - m1n);
        m0r = m0n; m1r = m1n;

        float rs0 = 0.0f, rs1 = 0.0f;
        #pragma unroll
        for (int nt = 0; nt < 4; nt++) {
            float p0 = to_tf32(__expf(sc[nt][0] - m0n));
            float p1 = to_tf32(__expf(sc[nt][1] - m0n));
            float p2 = to_tf32(__expf(sc[nt][2] - m1n));
            float p3 = to_tf32(__expf(sc[nt][3] - m1n));
            rs0 += p0 + p1;
            rs1 += p2 + p3;
            *(float2*)&Ps[wm + g    ][nt * 8 + 2 * t4] = make_float2(p0, p1);
            *(float2*)&Ps[wm + g + 8][nt * 8 + 2 * t4] = make_float2(p2, p3);
        }
        rs0 += __shfl_xor_sync(0xffffffffu, rs0, 1);
        rs0 += __shfl_xor_sync(0xffffffffu, rs0, 2);
        rs1 += __shfl_xor_sync(0xffffffffu, rs1, 1);
        rs1 += __shfl_xor_sync(0xffffffffu, rs1, 2);
        l0 = l0 * c0 + rs0;
        l1 = l1 * c1 + rs1;

        #pragma unroll
        for (int dt = 0; dt < 8; dt++) {
            oacc[dt][0] *= c0; oacc[dt][1] *= c0;
            oacc[dt][2] *= c1; oacc[dt][3] *= c1;
        }
        __syncwarp();   // Ps rows are warp-private

        // ---- O += P @ V (m16 x n64, k32) ----
        #pragma unroll
        for (int kc = 0; kc < 4; kc++) {
            int kr = kc * 8;
            float pa[4];
            pa[0] = Ps[wm + g    ][kr + t4    ];
            pa[1] = Ps[wm + g + 8][kr + t4    ];
            pa[2] = Ps[wm + g    ][kr + t4 + 4];
            pa[3] = Ps[wm + g + 8][kr + t4 + 4];
            #pragma unroll
            for (int dt = 0; dt < 8; dt++) {
                float b0 = Vt[(kr + t4    ) * 72 + dt * 8 + g];
                float b1 = Vt[(kr + t4 + 4) * 72 + dt * 8 + g];
                mma_tf32(oacc[dt], pa, b0, b1);
            }
        }
    }

    // ---- normalize + write out [B, S, H*D] ----
    float inv0 = 1.0f / l0;
    float inv1 = 1.0f / l1;
    int r0 = q0 + wm + g;
    int r1 = r0 + 8;
    #pragma unroll
    for (int dt = 0; dt < 8; dt++) {
        int d = dt * 8 + 2 * t4;
        float2 v0 = make_float2(oacc[dt][0] * inv0, oacc[dt][1] * inv0);
        float2 v1 = make_float2(oacc[dt][2] * inv1, oacc[dt][3] * inv1);
        *(float2*)&out[(b * SS + r0) * HIDN + h * HD + d] = v0;
        *(float2*)&out[(b * SS + r1) * HIDN + h * HD + d] = v1;
    }
}

// ---------------------------------------------------------------------------
extern "C" void kernel_launch(void* const* d_in, const int* in_sizes, int n_in,
                              void* d_out, int out_size) {
    const float* hs   = (const float*)d_in[0];
    const float* mask = (const float*)d_in[1];
    const float* Wq   = (const float*)d_in[2];
    const float* bq   = (const float*)d_in[3];
    const float* Wk   = (const float*)d_in[4];
    const float* bk   = (const float*)d_in[5];
    const float* Wv   = (const float*)d_in[6];
    const float* bv   = (const float*)d_in[7];
    float* out = (float*)d_out;

    static bool attr_set = false;
    if (!attr_set) {
        cudaFuncSetAttribute(attn_tf32,
                             cudaFuncAttributeMaxDynamicSharedMemorySize,
                             ATTN_SMEM_BYTES);
        cudaFuncSetAttribute(qkv_gemm_tf32,
                             cudaFuncAttributeMaxDynamicSharedMemorySize,
                             QKV_SMEM_BYTES);
        attr_set = true;
    }

    sincos_kernel<<<(SS * 32 + 255) / 256, 256>>>();
    prep_tf32<<<(NX4 + 3 * NW4) / 256, 256>>>((const float4*)hs,
                                              (const float4*)Wq,
                                              (const float4*)Wk,
                                              (const float4*)Wv);
    qkv_gemm_tf32<<<dim3(30, 32), 256, QKV_SMEM_BYTES>>>(bq, bk, bv);
    rope_kernel<<<(BB * NH * SS * 32) / 256, 256>>>();
    attn_tf32<<<dim3(SS / 64, BB * NH), 128, ATTN_SMEM_BYTES>>>(mask, out);
}